// round 4
// baseline (speedup 1.0000x reference)
#include <cuda_runtime.h>

// rate_loss: x (32,64,128,128) fp32 -> scalar f32
//
//  k_clear : zero global histogram + sum accumulator
//  k_hist  : one pass; u = floor(5x)+32; branch-free u8-packed per-thread
//            private counters (4 bins/word, conflict-free), 64-bin hot window;
//            outliers detected via OR-reduce + ballot per 8 elements (cold)
//  k_prep  : 1 block; vmin from lowest nonzero key; build table
//            {g[i], c[i] = hist_add[i] + 1e-8 - left_i*g[i]}  (fp64 math)
//  k_loss  : one pass; nl = fma(x, g[i], c[i]); one log2 per 4-element product
//  k_final : out = -sum / n

#define NBINS_MAX 200
#define BPU_I     5
#define GLEN      195   // NBINS_MAX - BPU
#define HLEN      196   // NBINS_MAX - BPU + 1
#define KBINS     1024  // global absolute-key histogram, keys [-512,511]
#define KOFF      512
#define WBINS     64    // hot window, keys [-32,32)  (|x| < 6.4)
#define WOFF      32
#define NWORD     16    // WBINS/4 u8-packed words per thread

__device__ unsigned int d_hist[KBINS];
__device__ double       d_sum;
__device__ float2       d_gh[GLEN];     // {g[i], c[i]}
__device__ float        d_voff;         // -5*vmin_new  (t = fma(x,5,voff))

// ---------------------------------------------------------------- clear
__global__ void k_clear() {
    int t = blockIdx.x * blockDim.x + threadIdx.x;
    if (t < KBINS) d_hist[t] = 0u;
    if (t == 0) d_sum = 0.0;
}

// ---------------------------------------------------------------- histogram
// sh layout: word[w][tid], w = u>>2, byte field = u&3.
// word index = w*256 + tid -> bank = tid & 31 : conflict-free always.
__device__ __forceinline__ unsigned int key_of(float v) {
    return (unsigned int)__float2int_rd(fmaf(v, 5.0f, 32.0f));   // u8 bin
}
__device__ __forceinline__ void bump(unsigned int u, unsigned char* __restrict__ sb) {
    // byte address: ((u>>2)*256 + tid)*4 + (u&3); sb already includes tid*4
    sb[(u >> 2) * 1024 + (u & 3u)] += 1;
}
__device__ __forceinline__ void bump_slow(unsigned int u) {
    int k = (int)u - WOFF;                      // raw key floor(5x)
    k = min(KOFF - 1, max(-KOFF, k));
    atomicAdd(&d_hist[k + KOFF], 1u);           // exact cold path
}

__global__ void __launch_bounds__(256) k_hist(const float* __restrict__ x,
                                              int n4, int n) {
    __shared__ unsigned int sh[NWORD * 256];    // 16 KB
    const int tid = threadIdx.x;
    #pragma unroll
    for (int i = tid; i < NWORD * 256; i += 256) sh[i] = 0u;
    __syncthreads();

    unsigned char* sb = (unsigned char*)sh + tid * 4;
    const float4* x4 = (const float4*)x;
    const int st = gridDim.x * 256;

    int idx = blockIdx.x * 256 + tid;
    for (; idx + st < n4; idx += 2 * st) {
        float4 a = __ldg(&x4[idx]);
        float4 b = __ldg(&x4[idx + st]);
        unsigned int u0 = key_of(a.x), u1 = key_of(a.y);
        unsigned int u2 = key_of(a.z), u3 = key_of(a.w);
        unsigned int u4 = key_of(b.x), u5 = key_of(b.y);
        unsigned int u6 = key_of(b.z), u7 = key_of(b.w);
        unsigned int bad = (u0 | u1 | u2 | u3 | u4 | u5 | u6 | u7) >= WBINS;
        if (!bad) {                              // hot: never-diverging path
            bump(u0, sb); bump(u1, sb); bump(u2, sb); bump(u3, sb);
            bump(u4, sb); bump(u5, sb); bump(u6, sb); bump(u7, sb);
        } else {                                 // cold: exact global atomics
            bump_slow(u0); bump_slow(u1); bump_slow(u2); bump_slow(u3);
            bump_slow(u4); bump_slow(u5); bump_slow(u6); bump_slow(u7);
        }
    }
    for (; idx < n4; idx += st) {
        float4 a = __ldg(&x4[idx]);
        unsigned int u0 = key_of(a.x), u1 = key_of(a.y);
        unsigned int u2 = key_of(a.z), u3 = key_of(a.w);
        if ((u0 | u1 | u2 | u3) < WBINS) {
            bump(u0, sb); bump(u1, sb); bump(u2, sb); bump(u3, sb);
        } else {
            bump_slow(u0); bump_slow(u1); bump_slow(u2); bump_slow(u3);
        }
    }
    for (int j = n4 * 4 + blockIdx.x * 256 + tid; j < n; j += st) {
        unsigned int u = key_of(__ldg(&x[j]));
        if (u < WBINS) bump(u, sb); else bump_slow(u);
    }
    __syncthreads();

    // merge: warp w reduces bins [w*8, w*8+8); lane-strided columns (bank-free)
    const int wid = tid >> 5, lane = tid & 31;
    for (int b = wid * 8; b < wid * 8 + 8; b++) {
        const unsigned int* col = sh + (b >> 2) * 256;
        const int shift = (b & 3) * 8;
        unsigned int s = 0;
        #pragma unroll
        for (int c = 0; c < 8; c++)
            s += (col[lane + 32 * c] >> shift) & 0xFFu;
        #pragma unroll
        for (int o = 16; o > 0; o >>= 1)
            s += __shfl_down_sync(0xffffffffu, s, o);
        if (lane == 0 && s)
            atomicAdd(&d_hist[b - WOFF + KOFF], s);
    }
}

// ---------------------------------------------------------------- prep (tiny)
__global__ void __launch_bounds__(256) k_prep(int n) {
    __shared__ unsigned int hist[KBINS];
    __shared__ int kmin_sh, kmax_sh;
    if (threadIdx.x == 0) { kmin_sh = KBINS; kmax_sh = -1; }
    for (int b = threadIdx.x; b < KBINS; b += 256) hist[b] = d_hist[b];
    __syncthreads();
    for (int b = threadIdx.x; b < KBINS; b += 256)
        if (hist[b]) { atomicMin(&kmin_sh, b); atomicMax(&kmax_sh, b); }
    __syncthreads();

    if (threadIdx.x == 0) {
        int kmin = kmin_sh - KOFF;                        // lowest key floor(5x)
        int jmin = (kmin >= 0) ? (kmin / 5) : -((-kmin + 4) / 5);  // floor(min)
        int vmin_i = jmin - 1;                            // vmin (integer)
        int shift = 5 * vmin_i;                           // hidx = k - 5*vmin

        float cnt[NBINS_MAX];
        for (int i = 0; i < NBINS_MAX; i++) cnt[i] = 0.0f;
        for (int b = kmin_sh; b <= kmax_sh; b++) {
            unsigned int c = hist[b];
            if (!c) continue;
            int t = (b - KOFF) - shift;
            t = min(NBINS_MAX - 1, max(0, t));
            cnt[t] += (float)c;
        }
        float inv_n = 1.0f / (float)n;
        float c_arr[NBINS_MAX + 1];
        c_arr[0] = 0.0f;
        for (int i = 0; i < NBINS_MAX; i++)
            c_arr[i + 1] = c_arr[i] + cnt[i] * inv_n;
        float hist_add[HLEN];
        for (int i = 0; i < HLEN; i++)
            hist_add[i] = c_arr[i + BPU_I] - c_arr[i];
        double vmn = (double)vmin_i + 0.5;
        for (int i = 0; i < GLEN; i++) {
            float g = (hist_add[i + 1] - hist_add[i]) * 5.0f;
            double left = vmn + (double)i * 0.2;
            double c = (double)hist_add[i] + 1e-8 - left * (double)g;
            d_gh[i] = make_float2(g, (float)c);
        }
        d_voff = (float)(-5.0 * vmn);
    }
}

// ---------------------------------------------------------------- loss
__device__ __forceinline__ float nl_one(float xv, float voff,
                                        const float2* __restrict__ gh) {
    int i = __float2int_rd(fmaf(xv, 5.0f, voff));   // lower clamp provably dead
    i = min(i, GLEN - 1);
    float2 p = gh[i];
    return fmaf(xv, p.x, p.y);                      // (x-left)*g + ha + 1e-8
}

__global__ void __launch_bounds__(256) k_loss(const float* __restrict__ x,
                                              int n4, int n) {
    __shared__ float2 gh[GLEN];
    __shared__ float wsum[8];
    for (int i = threadIdx.x; i < GLEN; i += 256) gh[i] = d_gh[i];
    float voff = d_voff;
    __syncthreads();

    const float4* x4 = (const float4*)x;
    const int st = gridDim.x * 256;
    float acc = 0.0f;

    int idx = blockIdx.x * 256 + threadIdx.x;
    for (; idx + 3 * st < n4; idx += 4 * st) {
        float4 a = __ldg(&x4[idx]);
        float4 b = __ldg(&x4[idx + st]);
        float4 c = __ldg(&x4[idx + 2 * st]);
        float4 d = __ldg(&x4[idx + 3 * st]);
        float pa = nl_one(a.x, voff, gh) * nl_one(a.y, voff, gh)
                 * nl_one(a.z, voff, gh) * nl_one(a.w, voff, gh);
        float pb = nl_one(b.x, voff, gh) * nl_one(b.y, voff, gh)
                 * nl_one(b.z, voff, gh) * nl_one(b.w, voff, gh);
        float pc = nl_one(c.x, voff, gh) * nl_one(c.y, voff, gh)
                 * nl_one(c.z, voff, gh) * nl_one(c.w, voff, gh);
        float pd = nl_one(d.x, voff, gh) * nl_one(d.y, voff, gh)
                 * nl_one(d.z, voff, gh) * nl_one(d.w, voff, gh);
        acc += __log2f(pa); acc += __log2f(pb);
        acc += __log2f(pc); acc += __log2f(pd);
    }
    for (; idx < n4; idx += st) {
        float4 a = __ldg(&x4[idx]);
        float pa = nl_one(a.x, voff, gh) * nl_one(a.y, voff, gh)
                 * nl_one(a.z, voff, gh) * nl_one(a.w, voff, gh);
        acc += __log2f(pa);
    }
    for (int j = n4 * 4 + blockIdx.x * 256 + threadIdx.x; j < n; j += st)
        acc += __log2f(nl_one(__ldg(&x[j]), voff, gh));

    #pragma unroll
    for (int o = 16; o > 0; o >>= 1)
        acc += __shfl_down_sync(0xffffffffu, acc, o);
    int wid = threadIdx.x >> 5, lid = threadIdx.x & 31;
    if (lid == 0) wsum[wid] = acc;
    __syncthreads();
    if (wid == 0) {
        float s = (lid < 8) ? wsum[lid] : 0.0f;
        #pragma unroll
        for (int o = 4; o > 0; o >>= 1)
            s += __shfl_down_sync(0xffffffffu, s, o);
        if (lid == 0) atomicAdd(&d_sum, (double)s);
    }
}

// ---------------------------------------------------------------- finalize
__global__ void k_final(float* __restrict__ out, int n) {
    out[0] = (float)(-d_sum / (double)n);
}

// ---------------------------------------------------------------- launch
extern "C" void kernel_launch(void* const* d_in, const int* in_sizes, int n_in,
                              void* d_out, int out_size) {
    const float* x = (const float*)d_in[0];
    int n  = in_sizes[0];
    int n4 = n >> 2;
    const int GRID = 1184;  // 8 per SM * 148

    k_clear<<<4, 256>>>();
    k_hist<<<GRID, 256>>>(x, n4, n);
    k_prep<<<1, 256>>>(n);
    k_loss<<<GRID, 256>>>(x, n4, n);
    k_final<<<1, 1>>>((float*)d_out, n);
}